// round 1
// baseline (speedup 1.0000x reference)
#include <cuda_runtime.h>

#define NB 16
#define SECL 16
#define WORDL 256
#define SLEN 4096
#define DIM 1024
#define FSZ 2
#define GATH (FSZ*WORDL)   // 512

// ---------------- scratch (device globals; no allocation) ----------------
__device__ float g_decfeat[NB*DIM];
__device__ int   g_topidx[NB*FSZ];
__device__ float g_topval[NB*FSZ];
__device__ float g_scores[NB*GATH];
__device__ float g_attn[NB*GATH];
__device__ float g_ctxpart[8*NB*DIM];

// accurate-enough tanh: 1 - 2/(e^{2x}+1), ex2/rcp MUFU (~1e-7 abs error)
__device__ __forceinline__ float fast_tanh(float x) {
    float e;
    asm("ex2.approx.f32 %0, %1;" : "=f"(e) : "f"(x * 2.8853900817779268f)); // 2*log2(e)
    float r;
    asm("rcp.approx.f32 %0, %1;" : "=f"(r) : "f"(e + 1.0f));
    return 1.0f - 2.0f * r;
}

// ---------------- K2: top-2 of focus[16,16] (jax tie rule) ----------------
__global__ void k2_topk(const float* __restrict__ focus) {
    int b = threadIdx.x;
    if (b < NB) {
        float best = -__int_as_float(0x7f800000); int bi = 0;
        for (int j = 0; j < SECL; j++) {
            float v = focus[b*SECL + j];
            if (v > best) { best = v; bi = j; }
        }
        float best2 = -__int_as_float(0x7f800000); int bi2 = 0;
        for (int j = 0; j < SECL; j++) {
            if (j == bi) continue;
            float v = focus[b*SECL + j];
            if (v > best2) { best2 = v; bi2 = j; }
        }
        g_topidx[b*FSZ]   = bi;  g_topval[b*FSZ]   = best;
        g_topidx[b*FSZ+1] = bi2; g_topval[b*FSZ+1] = best2;
    }
}

// ---------------- K1: dec_feature = dec_hidden @ W_dec^T + b_dec ----------------
// grid 64 blocks * 256 threads; each warp owns 2 output dims, loops all 16 batches.
__global__ __launch_bounds__(256) void k1_decproj(const float* __restrict__ h,
                                                  const float* __restrict__ W,
                                                  const float* __restrict__ bvec) {
    int warp = threadIdx.x >> 5;
    int lane = threadIdx.x & 31;
    int d0 = blockIdx.x*16 + warp*2;
    const float4* W0 = (const float4*)(W + (size_t)d0*DIM);
    const float4* W1 = (const float4*)(W + (size_t)(d0+1)*DIM);
    const float4* h4 = (const float4*)h;
    float acc0[NB], acc1[NB];
#pragma unroll
    for (int b = 0; b < NB; b++) { acc0[b] = 0.f; acc1[b] = 0.f; }
#pragma unroll
    for (int i = 0; i < 8; i++) {
        int kk = lane + i*32;           // float4 index into 1024-dim
        float4 w0 = __ldg(&W0[kk]);
        float4 w1 = __ldg(&W1[kk]);
#pragma unroll
        for (int b = 0; b < NB; b++) {
            float4 hb = __ldg(&h4[b*256 + kk]);
            acc0[b] = fmaf(w0.x, hb.x, fmaf(w0.y, hb.y, fmaf(w0.z, hb.z, fmaf(w0.w, hb.w, acc0[b]))));
            acc1[b] = fmaf(w1.x, hb.x, fmaf(w1.y, hb.y, fmaf(w1.z, hb.z, fmaf(w1.w, hb.w, acc1[b]))));
        }
    }
#pragma unroll
    for (int b = 0; b < NB; b++) {
#pragma unroll
        for (int o = 16; o > 0; o >>= 1) {
            acc0[b] += __shfl_xor_sync(0xffffffffu, acc0[b], o);
            acc1[b] += __shfl_xor_sync(0xffffffffu, acc1[b], o);
        }
    }
    if (lane == 0) {
        float bd0 = bvec[d0], bd1 = bvec[d0+1];
#pragma unroll
        for (int b = 0; b < NB; b++) {
            g_decfeat[b*DIM + d0]     = acc0[b] + bd0;
            g_decfeat[b*DIM + d0 + 1] = acc1[b] + bd1;
        }
    }
}

// ---------------- K3: scores on gathered sections only ----------------
// one warp per gathered position; grid 1024 blocks * 256 threads = 8192 warps
__global__ __launch_bounds__(256) void k3_scores(const float* __restrict__ enc_feature,
                                                 const float* __restrict__ coverage,
                                                 const float* __restrict__ vvec,
                                                 const float* __restrict__ w_cov) {
    int warp = threadIdx.x >> 5;
    int lane = threadIdx.x & 31;
    int gw = blockIdx.x*8 + warp;
    int b = gw >> 9;
    int r = gw & 511;
    int f = r >> 8;
    int sec = g_topidx[b*FSZ + f];
    int s = sec*WORDL + (r & 255);
    float cov = coverage[b*SLEN + s];
    const float4* ef  = (const float4*)(enc_feature + ((size_t)(b*SLEN + s))*DIM);
    const float4* df  = (const float4*)(g_decfeat + b*DIM);
    const float4* v4  = (const float4*)vvec;
    const float4* wc4 = (const float4*)w_cov;
    float acc = 0.f;
#pragma unroll
    for (int i = 0; i < 8; i++) {
        int kk = lane + i*32;
        float4 e  = __ldg(&ef[kk]);
        float4 dd = df[kk];
        float4 vv = __ldg(&v4[kk]);
        float4 wc = __ldg(&wc4[kk]);
        acc += vv.x * fast_tanh(fmaf(cov, wc.x, e.x + dd.x));
        acc += vv.y * fast_tanh(fmaf(cov, wc.y, e.y + dd.y));
        acc += vv.z * fast_tanh(fmaf(cov, wc.z, e.z + dd.z));
        acc += vv.w * fast_tanh(fmaf(cov, wc.w, e.w + dd.w));
    }
#pragma unroll
    for (int o = 16; o > 0; o >>= 1) acc += __shfl_xor_sync(0xffffffffu, acc, o);
    if (lane == 0) g_scores[b*GATH + r] = acc;
}

// ---------------- block reduce helper (512 threads) ----------------
__device__ __forceinline__ float blkred(float v, float* red, bool is_max) {
#pragma unroll
    for (int o = 16; o > 0; o >>= 1) {
        float t = __shfl_xor_sync(0xffffffffu, v, o);
        v = is_max ? fmaxf(v, t) : (v + t);
    }
    __syncthreads();
    if ((threadIdx.x & 31) == 0) red[threadIdx.x >> 5] = v;
    __syncthreads();
    if (threadIdx.x < 32) {
        float x = (threadIdx.x < 16) ? red[threadIdx.x]
                                     : (is_max ? -__int_as_float(0x7f800000) : 0.f);
#pragma unroll
        for (int o = 8; o > 0; o >>= 1) {
            float t = __shfl_xor_sync(0xffffffffu, x, o);
            x = is_max ? fmaxf(x, t) : (x + t);
        }
        if (threadIdx.x == 0) red[0] = x;
    }
    __syncthreads();
    return red[0];
}

// ---------------- K4: softmax + double renorm + scatter + coverage ----------------
// one block per batch, 512 threads (one per gathered position)
__global__ __launch_bounds__(512) void k4_softmax(const float* __restrict__ enc_mask,
                                                  const float* __restrict__ coverage,
                                                  float* __restrict__ out) {
    __shared__ float red[16];
    __shared__ float sh_a[GATH];
    int b = blockIdx.x;
    int j = threadIdx.x;
    int f = j >> 8;
    int sec = g_topidx[b*FSZ + f];
    int s = sec*WORDL + (j & 255);
    float sc = g_scores[b*GATH + j];
    float m  = enc_mask[b*SLEN + s];

    float mx   = blkred(sc, red, true);
    float e    = __expf(sc - mx);
    float sum  = blkred(e, red, false);
    float a0   = (e / sum) * m;
    float sum2 = blkred(a0, red, false);
    float a1   = g_topval[b*FSZ + f] * (a0 / sum2);
    float sum3 = blkred(a1, red, false);
    float a    = a1 / sum3;

    g_attn[b*GATH + j] = a;
    sh_a[j] = a;
    __syncthreads();

    int i0 = g_topidx[b*FSZ], i1 = g_topidx[b*FSZ + 1];
    float* oa = out + NB*DIM + b*SLEN;               // attn_dist
    float* oc = out + NB*DIM + NB*SLEN + b*SLEN;     // coverage_out
    for (int i = j; i < SLEN; i += 512) {
        int si = i >> 8, w = i & 255;
        float av = 0.f;
        if (si == i0)      av = sh_a[w];
        else if (si == i1) av = sh_a[WORDL + w];
        oa[i] = av;
        oc[i] = coverage[b*SLEN + i] + av;
    }
}

// ---------------- K5: context partials (gathered GEMV) ----------------
// grid (8 d-chunks, 16 b, 8 s-chunks of 64 words), 128 threads
__global__ __launch_bounds__(128) void k5_ctx(const float* __restrict__ enc_output) {
    __shared__ float sh_a[64];
    int b   = blockIdx.y;
    int sc8 = blockIdx.z;
    int f   = sc8 >> 2;
    int w0  = (sc8 & 3) * 64;
    int d   = blockIdx.x*128 + threadIdx.x;
    if (threadIdx.x < 64)
        sh_a[threadIdx.x] = g_attn[b*GATH + f*WORDL + w0 + threadIdx.x];
    __syncthreads();
    int sec = g_topidx[b*FSZ + f];
    const float* base = enc_output + ((size_t)(b*SLEN + sec*WORDL + w0))*DIM + d;
    float a0 = 0.f, a1 = 0.f, a2 = 0.f, a3 = 0.f;
#pragma unroll 4
    for (int w = 0; w < 64; w += 4) {
        a0 = fmaf(sh_a[w],     __ldg(&base[(size_t)(w)    *DIM]), a0);
        a1 = fmaf(sh_a[w + 1], __ldg(&base[(size_t)(w + 1)*DIM]), a1);
        a2 = fmaf(sh_a[w + 2], __ldg(&base[(size_t)(w + 2)*DIM]), a2);
        a3 = fmaf(sh_a[w + 3], __ldg(&base[(size_t)(w + 3)*DIM]), a3);
    }
    g_ctxpart[(sc8*NB + b)*DIM + d] = (a0 + a1) + (a2 + a3);
}

// ---------------- K6: combine context partials ----------------
__global__ void k6_combine(float* __restrict__ out) {
    int i = blockIdx.x*256 + threadIdx.x;   // i < 16*1024
    float sum = 0.f;
#pragma unroll
    for (int p = 0; p < 8; p++) sum += g_ctxpart[p*(NB*DIM) + i];
    out[i] = sum;
}

extern "C" void kernel_launch(void* const* d_in, const int* in_sizes, int n_in,
                              void* d_out, int out_size) {
    const float* dec_hidden  = (const float*)d_in[0];
    const float* enc_output  = (const float*)d_in[1];
    const float* enc_feature = (const float*)d_in[2];
    const float* enc_mask    = (const float*)d_in[3];
    // d_in[4] = sec_attn (unused by reference)
    const float* coverage    = (const float*)d_in[5];
    const float* focus       = (const float*)d_in[6];
    const float* W_dec       = (const float*)d_in[7];
    const float* b_dec       = (const float*)d_in[8];
    const float* vvec        = (const float*)d_in[9];
    const float* w_cov       = (const float*)d_in[10];
    float* out = (float*)d_out;

    k2_topk<<<1, 32>>>(focus);
    k1_decproj<<<64, 256>>>(dec_hidden, W_dec, b_dec);
    k3_scores<<<1024, 256>>>(enc_feature, coverage, vvec, w_cov);
    k4_softmax<<<16, 512>>>(enc_mask, coverage, out);
    k5_ctx<<<dim3(8, 16, 8), 128>>>(enc_output);
    k6_combine<<<64, 256>>>(out);
}

// round 2
// speedup vs baseline: 1.1665x; 1.1665x over previous
#include <cuda_runtime.h>

#define NB 16
#define SECL 16
#define WORDL 256
#define SLEN 4096
#define DIM 1024
#define FSZ 2
#define GATH (FSZ*WORDL)   // 512

// ---------------- scratch (device globals; no allocation) ----------------
__device__ float g_decfeat[NB*DIM];
__device__ float g_scores[NB*GATH];
__device__ float g_attn[NB*GATH];
__device__ float g_ctxpart[8*NB*DIM];

// accurate-enough tanh: 1 - 2/(e^{2x}+1), ex2/rcp MUFU (~1e-7 abs error)
__device__ __forceinline__ float fast_tanh(float x) {
    float e;
    asm("ex2.approx.f32 %0, %1;" : "=f"(e) : "f"(x * 2.8853900817779268f)); // 2*log2(e)
    float r;
    asm("rcp.approx.f32 %0, %1;" : "=f"(r) : "f"(e + 1.0f));
    return 1.0f - 2.0f * r;
}

// inline top-2 of focus[b] (jax first-occurrence tie rule); 16 floats, L1/L2 hot
__device__ __forceinline__ void top2_focus(const float* __restrict__ focus, int b,
                                           int& i0, int& i1, float& v0, float& v1) {
    const float* f = focus + b*SECL;
    v0 = -__int_as_float(0x7f800000); i0 = 0;
#pragma unroll
    for (int j = 0; j < SECL; j++) { float x = __ldg(&f[j]); if (x > v0) { v0 = x; i0 = j; } }
    v1 = -__int_as_float(0x7f800000); i1 = 0;
#pragma unroll
    for (int j = 0; j < SECL; j++) {
        if (j == i0) continue;
        float x = __ldg(&f[j]); if (x > v1) { v1 = x; i1 = j; }
    }
}

// ---------------- K1: dec_feature = dec_hidden @ W_dec^T + b_dec ----------------
// 128 blocks * 256 threads; each warp owns 1 output dim, loops all 16 batches.
__global__ __launch_bounds__(256) void k1_decproj(const float* __restrict__ h,
                                                  const float* __restrict__ W,
                                                  const float* __restrict__ bvec) {
    int warp = threadIdx.x >> 5;
    int lane = threadIdx.x & 31;
    int d = blockIdx.x*8 + warp;
    const float4* Wd = (const float4*)(W + (size_t)d*DIM);
    const float4* h4 = (const float4*)h;
    float acc[NB];
#pragma unroll
    for (int b = 0; b < NB; b++) acc[b] = 0.f;
#pragma unroll
    for (int i = 0; i < 8; i++) {
        int kk = lane + i*32;           // float4 index into 1024-dim
        float4 w = __ldg(&Wd[kk]);
#pragma unroll
        for (int b = 0; b < NB; b++) {
            float4 hb = __ldg(&h4[b*256 + kk]);
            acc[b] = fmaf(w.x, hb.x, fmaf(w.y, hb.y, fmaf(w.z, hb.z, fmaf(w.w, hb.w, acc[b]))));
        }
    }
#pragma unroll
    for (int b = 0; b < NB; b++) {
#pragma unroll
        for (int o = 16; o > 0; o >>= 1)
            acc[b] += __shfl_xor_sync(0xffffffffu, acc[b], o);
    }
    if (lane == 0) {
        float bd = bvec[d];
#pragma unroll
        for (int b = 0; b < NB; b++)
            g_decfeat[b*DIM + d] = acc[b] + bd;
    }
}

// ---------------- K3: scores on gathered sections only ----------------
// one warp per gathered position; grid 1024 blocks * 256 threads = 8192 warps
__global__ __launch_bounds__(256) void k3_scores(const float* __restrict__ enc_feature,
                                                 const float* __restrict__ coverage,
                                                 const float* __restrict__ vvec,
                                                 const float* __restrict__ w_cov,
                                                 const float* __restrict__ focus) {
    int warp = threadIdx.x >> 5;
    int lane = threadIdx.x & 31;
    int gw = blockIdx.x*8 + warp;
    int b = gw >> 9;
    int r = gw & 511;
    int f = r >> 8;
    int i0, i1; float v0, v1;
    top2_focus(focus, b, i0, i1, v0, v1);
    int sec = f ? i1 : i0;
    int s = sec*WORDL + (r & 255);
    float cov = coverage[b*SLEN + s];
    const float4* ef  = (const float4*)(enc_feature + ((size_t)(b*SLEN + s))*DIM);
    const float4* df  = (const float4*)(g_decfeat + b*DIM);
    const float4* v4  = (const float4*)vvec;
    const float4* wc4 = (const float4*)w_cov;
    float acc = 0.f;
#pragma unroll
    for (int i = 0; i < 8; i++) {
        int kk = lane + i*32;
        float4 e  = __ldg(&ef[kk]);
        float4 dd = df[kk];
        float4 vv = __ldg(&v4[kk]);
        float4 wc = __ldg(&wc4[kk]);
        acc += vv.x * fast_tanh(fmaf(cov, wc.x, e.x + dd.x));
        acc += vv.y * fast_tanh(fmaf(cov, wc.y, e.y + dd.y));
        acc += vv.z * fast_tanh(fmaf(cov, wc.z, e.z + dd.z));
        acc += vv.w * fast_tanh(fmaf(cov, wc.w, e.w + dd.w));
    }
#pragma unroll
    for (int o = 16; o > 0; o >>= 1) acc += __shfl_xor_sync(0xffffffffu, acc, o);
    if (lane == 0) g_scores[b*GATH + r] = acc;
}

// ---------------- block reduce helper (512 threads) ----------------
__device__ __forceinline__ float blkred(float v, float* red, bool is_max) {
#pragma unroll
    for (int o = 16; o > 0; o >>= 1) {
        float t = __shfl_xor_sync(0xffffffffu, v, o);
        v = is_max ? fmaxf(v, t) : (v + t);
    }
    __syncthreads();
    if ((threadIdx.x & 31) == 0) red[threadIdx.x >> 5] = v;
    __syncthreads();
    if (threadIdx.x < 32) {
        float x = (threadIdx.x < 16) ? red[threadIdx.x]
                                     : (is_max ? -__int_as_float(0x7f800000) : 0.f);
#pragma unroll
        for (int o = 8; o > 0; o >>= 1) {
            float t = __shfl_xor_sync(0xffffffffu, x, o);
            x = is_max ? fmaxf(x, t) : (x + t);
        }
        if (threadIdx.x == 0) red[0] = x;
    }
    __syncthreads();
    return red[0];
}

// ---------------- K4: softmax + double renorm -> g_attn only ----------------
// one block per batch, 512 threads (one per gathered position)
__global__ __launch_bounds__(512) void k4_softmax(const float* __restrict__ enc_mask,
                                                  const float* __restrict__ focus) {
    __shared__ float red[16];
    int b = blockIdx.x;
    int j = threadIdx.x;
    int f = j >> 8;
    int i0, i1; float v0, v1;
    top2_focus(focus, b, i0, i1, v0, v1);
    int sec = f ? i1 : i0;
    float tv  = f ? v1 : v0;
    int s = sec*WORDL + (j & 255);
    float sc = g_scores[b*GATH + j];
    float m  = enc_mask[b*SLEN + s];

    float mx   = blkred(sc, red, true);
    float e    = __expf(sc - mx);
    float sum  = blkred(e, red, false);
    float a0   = (e / sum) * m;
    float sum2 = blkred(a0, red, false);
    float a1   = tv * (a0 / sum2);
    float sum3 = blkred(a1, red, false);
    g_attn[b*GATH + j] = a1 / sum3;
}

// ---------------- K5: context partials (gathered GEMV) ----------------
// grid (8 d-chunks, 16 b, 8 s-chunks of 64 words), 128 threads
__global__ __launch_bounds__(128) void k5_ctx(const float* __restrict__ enc_output,
                                              const float* __restrict__ focus) {
    __shared__ float sh_a[64];
    int b   = blockIdx.y;
    int sc8 = blockIdx.z;
    int f   = sc8 >> 2;
    int w0  = (sc8 & 3) * 64;
    int d   = blockIdx.x*128 + threadIdx.x;
    if (threadIdx.x < 64)
        sh_a[threadIdx.x] = g_attn[b*GATH + f*WORDL + w0 + threadIdx.x];
    __syncthreads();
    int i0, i1; float v0, v1;
    top2_focus(focus, b, i0, i1, v0, v1);
    int sec = f ? i1 : i0;
    const float* base = enc_output + ((size_t)(b*SLEN + sec*WORDL + w0))*DIM + d;
    float a0 = 0.f, a1 = 0.f, a2 = 0.f, a3 = 0.f;
#pragma unroll 4
    for (int w = 0; w < 64; w += 4) {
        a0 = fmaf(sh_a[w],     __ldg(&base[(size_t)(w)    *DIM]), a0);
        a1 = fmaf(sh_a[w + 1], __ldg(&base[(size_t)(w + 1)*DIM]), a1);
        a2 = fmaf(sh_a[w + 2], __ldg(&base[(size_t)(w + 2)*DIM]), a2);
        a3 = fmaf(sh_a[w + 3], __ldg(&base[(size_t)(w + 3)*DIM]), a3);
    }
    g_ctxpart[(sc8*NB + b)*DIM + d] = (a0 + a1) + (a2 + a3);
}

// ---------------- K6: fused epilogue — context combine + wide scatter ----------------
// blocks [0,16): sum 8 context partials (float4). blocks [16,80): attn_dist + coverage_out.
__global__ __launch_bounds__(256) void k6_epilogue(const float* __restrict__ coverage,
                                                   const float* __restrict__ focus,
                                                   float* __restrict__ out) {
    if (blockIdx.x < 16) {
        int i = blockIdx.x*256 + threadIdx.x;       // float4 index, 4096 total
        const float4* cp = (const float4*)g_ctxpart;
        float4 s = cp[i];
#pragma unroll
        for (int p = 1; p < 8; p++) {
            float4 t = cp[p*(NB*DIM/4) + i];
            s.x += t.x; s.y += t.y; s.z += t.z; s.w += t.w;
        }
        ((float4*)out)[i] = s;
    } else {
        int g = (blockIdx.x - 16)*256 + threadIdx.x; // float4 index, 16384 total
        int b = g >> 10;                             // 1024 float4 per batch
        int p4 = g & 1023;
        int pos = p4 << 2;                           // word position 0..4095
        int si = pos >> 8;
        int w  = pos & 255;
        int i0, i1; float v0, v1;
        top2_focus(focus, b, i0, i1, v0, v1);
        float4 av = make_float4(0.f, 0.f, 0.f, 0.f);
        if (si == i0)      av = *(const float4*)(g_attn + b*GATH + w);
        else if (si == i1) av = *(const float4*)(g_attn + b*GATH + WORDL + w);
        float4 cv = __ldg((const float4*)(coverage + b*SLEN) + p4);
        float4* oa = (float4*)(out + NB*DIM + b*SLEN);
        float4* oc = (float4*)(out + NB*DIM + NB*SLEN + b*SLEN);
        oa[p4] = av;
        oc[p4] = make_float4(cv.x + av.x, cv.y + av.y, cv.z + av.z, cv.w + av.w);
    }
}

extern "C" void kernel_launch(void* const* d_in, const int* in_sizes, int n_in,
                              void* d_out, int out_size) {
    const float* dec_hidden  = (const float*)d_in[0];
    const float* enc_output  = (const float*)d_in[1];
    const float* enc_feature = (const float*)d_in[2];
    const float* enc_mask    = (const float*)d_in[3];
    // d_in[4] = sec_attn (unused by reference)
    const float* coverage    = (const float*)d_in[5];
    const float* focus       = (const float*)d_in[6];
    const float* W_dec       = (const float*)d_in[7];
    const float* b_dec       = (const float*)d_in[8];
    const float* vvec        = (const float*)d_in[9];
    const float* w_cov       = (const float*)d_in[10];
    float* out = (float*)d_out;

    k1_decproj<<<128, 256>>>(dec_hidden, W_dec, b_dec);
    k3_scores<<<1024, 256>>>(enc_feature, coverage, vvec, w_cov, focus);
    k4_softmax<<<16, 512>>>(enc_mask, focus);
    k5_ctx<<<dim3(8, 16, 8), 128>>>(enc_output, focus);
    k6_epilogue<<<80, 256>>>(coverage, focus, out);
}